// round 4
// baseline (speedup 1.0000x reference)
#include <cuda_runtime.h>
#include <cstdint>

#define SDIM 2048
#define BDIM 16
#define DDIM 64
#define DVDIM 512
#define QB 64
#define JB 64
#define NT 512

// Scratch: K^T, Kt[d][s] = sum_c m[d][c] * n[s][c]   (512 KB)
__device__ float g_Kt[DDIM * SDIM];

// ---------------------------------------------------------------------------
// Kernel 1: build K^T  (tiny: 67M FMA)
// ---------------------------------------------------------------------------
__global__ void k_build_kt(const float* __restrict__ m, const float* __restrict__ n) {
    __shared__ float sn[DVDIM];
    const int s = blockIdx.x;
    const float4* n4 = reinterpret_cast<const float4*>(n + (size_t)s * DVDIM);
    float4* sn4 = reinterpret_cast<float4*>(sn);
    for (int c = threadIdx.x; c < DVDIM / 4; c += blockDim.x) sn4[c] = n4[c];
    __syncthreads();
    const int d = threadIdx.x;  // blockDim = 64
    const float* mr = m + (size_t)d * DVDIM;
    float acc = 0.f;
#pragma unroll 8
    for (int c = 0; c < DVDIM; ++c) acc += mr[c] * sn[c];
    g_Kt[d * SDIM + s] = acc;
}

// ---------------------------------------------------------------------------
// JAX threefry2x32, key = jax.random.key(42) -> (k0, k1) = (0, 42)
// ---------------------------------------------------------------------------
__device__ __forceinline__ uint2 tf2x32(uint32_t x0, uint32_t x1) {
    const uint32_t K1 = 42u;
    const uint32_t K2 = 0x1BD11BDAu ^ 42u;  // k0 ^ k1 ^ 0x1BD11BDA with k0=0
#define TFR(r) { x0 += x1; x1 = __funnelshift_l(x1, x1, (r)); x1 ^= x0; }
    /* x0 += ks[0] (=0) */ x1 += K1;
    TFR(13) TFR(15) TFR(26) TFR(6)
    x0 += K1; x1 += K2 + 1u;
    TFR(17) TFR(29) TFR(16) TFR(24)
    x0 += K2; x1 += 0u + 2u;
    TFR(13) TFR(15) TFR(26) TFR(6)
    /* x0 += 0 */ x1 += K1 + 3u;
    TFR(17) TFR(29) TFR(16) TFR(24)
    x0 += K1; x1 += K2 + 4u;
    TFR(13) TFR(15) TFR(26) TFR(6)
    x0 += K2; x1 += 0u + 5u;
#undef TFR
    return make_uint2(x0, x1);
}

// Partitionable-threefry mask bit for flat element index f (< 2^32):
// counter is the 64-bit flat index split as (hi, lo) = (0, f); 32-bit draw is
// the XOR of the two threefry output words. u = bits-to-[0,1); keep iff u < 0.75.
__device__ __forceinline__ bool keep_mask(uint32_t f) {
    uint2 r = tf2x32(0u, f);
    uint32_t bits = r.x ^ r.y;
    float u = __uint_as_float((bits >> 9) | 0x3F800000u) - 1.0f;  // [0,1)
    return u < 0.75f;  // keep prob = 1 - 0.25
}

// ---------------------------------------------------------------------------
// Kernel 2: fused flash attention with online softmax + threefry dropout
//   grid = 512 (16 batches x 32 query blocks), block = 512 threads
// ---------------------------------------------------------------------------
__global__ __launch_bounds__(NT) void k_attn(
    const float* __restrict__ x1,
    const float* __restrict__ V,    // = q [S, 512]
    float* __restrict__ out) {
    extern __shared__ float sm[];
    float* sQt  = sm;                    // [D][QB]  (transposed Q)
    float* sKt  = sQt + DDIM * QB;       // [D][JB]  (transposed K tile)
    float* sP   = sKt + DDIM * JB;       // [QB][JB] (dropped, unnormalized probs)
    float* row_m = sP + QB * JB;         // [QB]
    float* row_l = row_m + QB;           // [QB]
    float* row_a = row_l + QB;           // [QB]

    const int t  = threadIdx.x;
    const int blk = blockIdx.x;          // 0..511
    const int b  = blk >> 5;             // batch 0..15
    const int i0 = (blk & 31) * QB;      // query row base within batch

    if (t < QB) { row_m[t] = -3.402823466e38f; row_l[t] = 0.f; }

    // load Q block transposed: sQt[d][r] = x1[b][i0+r][d]
    {
        const float* xb = x1 + ((size_t)b * SDIM + i0) * DDIM;
        for (int idx = t; idx < QB * (DDIM / 4); idx += NT) {
            int r  = idx >> 4;
            int d4 = (idx & 15) << 2;
            float4 v = *reinterpret_cast<const float4*>(xb + r * DDIM + d4);
            sQt[(d4 + 0) * QB + r] = v.x;
            sQt[(d4 + 1) * QB + r] = v.y;
            sQt[(d4 + 2) * QB + r] = v.z;
            sQt[(d4 + 3) * QB + r] = v.w;
        }
    }

    // PV mapping: thread owns rows rg*8..+7, cols cg*8..+7
    const int cg = t & 63;
    const int rg = t >> 6;
    float4 o0[8], o1[8];
#pragma unroll
    for (int u = 0; u < 8; ++u) {
        o0[u] = make_float4(0.f, 0.f, 0.f, 0.f);
        o1[u] = make_float4(0.f, 0.f, 0.f, 0.f);
    }

    // S-phase mapping (t < 256): 2 rows x 8 cols per thread
    const int jg = t & 7;
    const int r0 = (t >> 3) * 2;
    const float scale = 1.f / 64.f;
    const float inv_keep = 1.f / 0.75f;

    for (int tile = 0; tile < SDIM / JB; ++tile) {
        const int j0 = tile * JB;
        __syncthreads();  // previous PV done: safe to overwrite sKt / sP / row stats

        // load K tile: sKt[d][jj] = g_Kt[d][j0+jj]
        for (int idx = t; idx < DDIM * (JB / 4); idx += NT) {
            int d  = idx >> 4;
            int c4 = (idx & 15) << 2;
            *reinterpret_cast<float4*>(sKt + d * JB + c4) =
                *reinterpret_cast<const float4*>(g_Kt + d * SDIM + j0 + c4);
        }
        __syncthreads();

        if (t < 256) {
            float a0[8], a1[8];
#pragma unroll
            for (int jj = 0; jj < 8; ++jj) { a0[jj] = 0.f; a1[jj] = 0.f; }
#pragma unroll 8
            for (int d = 0; d < DDIM; ++d) {
                float q0 = sQt[d * QB + r0];
                float q1 = sQt[d * QB + r0 + 1];
                float4 ka = *reinterpret_cast<const float4*>(sKt + d * JB + jg * 8);
                float4 kb = *reinterpret_cast<const float4*>(sKt + d * JB + jg * 8 + 4);
                a0[0] += q0 * ka.x; a0[1] += q0 * ka.y; a0[2] += q0 * ka.z; a0[3] += q0 * ka.w;
                a0[4] += q0 * kb.x; a0[5] += q0 * kb.y; a0[6] += q0 * kb.z; a0[7] += q0 * kb.w;
                a1[0] += q1 * ka.x; a1[1] += q1 * ka.y; a1[2] += q1 * ka.z; a1[3] += q1 * ka.w;
                a1[4] += q1 * kb.x; a1[5] += q1 * kb.y; a1[6] += q1 * kb.z; a1[7] += q1 * kb.w;
            }
            float mx0 = -3.402823466e38f, mx1 = -3.402823466e38f;
#pragma unroll
            for (int jj = 0; jj < 8; ++jj) {
                a0[jj] *= scale; mx0 = fmaxf(mx0, a0[jj]);
                a1[jj] *= scale; mx1 = fmaxf(mx1, a1[jj]);
            }
#pragma unroll
            for (int w = 1; w < 8; w <<= 1) {
                mx0 = fmaxf(mx0, __shfl_xor_sync(0xffffffffu, mx0, w));
                mx1 = fmaxf(mx1, __shfl_xor_sync(0xffffffffu, mx1, w));
            }
            float om0 = row_m[r0], om1 = row_m[r0 + 1];
            float nm0 = fmaxf(om0, mx0), nm1 = fmaxf(om1, mx1);
            float al0 = __expf(om0 - nm0), al1 = __expf(om1 - nm1);
            float s0 = 0.f, s1 = 0.f;
#pragma unroll
            for (int jj = 0; jj < 8; ++jj) {
                a0[jj] = __expf(a0[jj] - nm0); s0 += a0[jj];
                a1[jj] = __expf(a1[jj] - nm1); s1 += a1[jj];
            }
#pragma unroll
            for (int w = 1; w < 8; w <<= 1) {
                s0 += __shfl_xor_sync(0xffffffffu, s0, w);
                s1 += __shfl_xor_sync(0xffffffffu, s1, w);
            }
            if (jg == 0) {
                row_l[r0]     = row_l[r0]     * al0 + s0;  row_m[r0]     = nm0;  row_a[r0]     = al0;
                row_l[r0 + 1] = row_l[r0 + 1] * al1 + s1;  row_m[r0 + 1] = nm1;  row_a[r0 + 1] = al1;
            }
            // dropout (pre-normalization; denominator unaffected) + write P tile
            const uint32_t fb0 = ((uint32_t)b << 22) | ((uint32_t)(i0 + r0) << 11) | (uint32_t)(j0 + jg * 8);
            const uint32_t fb1 = fb0 + 2048u;  // next row
#pragma unroll
            for (int jj = 0; jj < 8; ++jj) {
                a0[jj] = keep_mask(fb0 + jj) ? a0[jj] * inv_keep : 0.f;
                a1[jj] = keep_mask(fb1 + jj) ? a1[jj] * inv_keep : 0.f;
            }
            *reinterpret_cast<float4*>(sP + r0 * JB + jg * 8)       = make_float4(a0[0], a0[1], a0[2], a0[3]);
            *reinterpret_cast<float4*>(sP + r0 * JB + jg * 8 + 4)   = make_float4(a0[4], a0[5], a0[6], a0[7]);
            *reinterpret_cast<float4*>(sP + (r0 + 1) * JB + jg * 8)     = make_float4(a1[0], a1[1], a1[2], a1[3]);
            *reinterpret_cast<float4*>(sP + (r0 + 1) * JB + jg * 8 + 4) = make_float4(a1[4], a1[5], a1[6], a1[7]);
        }
        __syncthreads();

        // PV: O += P_tile @ V_tile, with online rescale by alpha
        {
            const float* pr = sP + rg * 8 * JB;
            float av[8];
#pragma unroll
            for (int u = 0; u < 8; ++u) av[u] = row_a[rg * 8 + u];
#pragma unroll
            for (int u = 0; u < 8; ++u) {
                o0[u].x *= av[u]; o0[u].y *= av[u]; o0[u].z *= av[u]; o0[u].w *= av[u];
                o1[u].x *= av[u]; o1[u].y *= av[u]; o1[u].z *= av[u]; o1[u].w *= av[u];
            }
            const float* vp = V + (size_t)j0 * DVDIM + cg * 8;
            for (int j4 = 0; j4 < JB; j4 += 4) {
                float4 pv[8];
#pragma unroll
                for (int u = 0; u < 8; ++u)
                    pv[u] = *reinterpret_cast<const float4*>(pr + u * JB + j4);
#pragma unroll
                for (int jj = 0; jj < 4; ++jj) {
                    const float* vr = vp + (size_t)(j4 + jj) * DVDIM;
                    float4 v0 = *reinterpret_cast<const float4*>(vr);
                    float4 v1 = *reinterpret_cast<const float4*>(vr + 4);
#pragma unroll
                    for (int u = 0; u < 8; ++u) {
                        float p = (jj == 0) ? pv[u].x : (jj == 1) ? pv[u].y
                                : (jj == 2) ? pv[u].z : pv[u].w;
                        o0[u].x += p * v0.x; o0[u].y += p * v0.y;
                        o0[u].z += p * v0.z; o0[u].w += p * v0.w;
                        o1[u].x += p * v1.x; o1[u].y += p * v1.y;
                        o1[u].z += p * v1.z; o1[u].w += p * v1.w;
                    }
                }
            }
        }
    }
    __syncthreads();

    // normalize by softmax denominator and store
    {
        float* ob = out + ((size_t)b * SDIM + i0 + rg * 8) * DVDIM + cg * 8;
#pragma unroll
        for (int u = 0; u < 8; ++u) {
            float inv = 1.0f / row_l[rg * 8 + u];
            float4 w0 = o0[u], w1 = o1[u];
            w0.x *= inv; w0.y *= inv; w0.z *= inv; w0.w *= inv;
            w1.x *= inv; w1.y *= inv; w1.z *= inv; w1.w *= inv;
            *reinterpret_cast<float4*>(ob + (size_t)u * DVDIM)     = w0;
            *reinterpret_cast<float4*>(ob + (size_t)u * DVDIM + 4) = w1;
        }
    }
}

// ---------------------------------------------------------------------------
extern "C" void kernel_launch(void* const* d_in, const int* in_sizes, int n_in,
                              void* d_out, int out_size) {
    const float* x1 = (const float*)d_in[0];  // [16,2048,64]
    const float* m  = (const float*)d_in[1];  // [64,512]
    const float* n  = (const float*)d_in[2];  // [2048,512]
    const float* q  = (const float*)d_in[3];  // [2048,512]
    float* out = (float*)d_out;               // [16,2048,512]

    const int smem_bytes = (3 * 64 * 64 + 3 * 64) * (int)sizeof(float);  // 49920
    cudaFuncSetAttribute(k_attn, cudaFuncAttributeMaxDynamicSharedMemorySize, smem_bytes);

    k_build_kt<<<SDIM, DDIM>>>(m, n);
    k_attn<<<BDIM * (SDIM / QB), NT, smem_bytes>>>(x1, q, out);
}

// round 9
// speedup vs baseline: 1.4579x; 1.4579x over previous
#include <cuda_runtime.h>
#include <cstdint>

#define SDIM 2048
#define BDIM 16
#define DDIM 64
#define DVDIM 512
#define QB 64               // query rows per CTA
#define JT 64               // j-tile width
#define NT 512              // threads per CTA (16 warps)

// ---------------- scratch (__device__ globals) ------------------------------
__device__ float g_Kt[DDIM * SDIM];      // K'[d][s] = (m @ n^T)[d][s] / 64
__device__ float g_Vr[SDIM * DVDIM];     // V tf32(rna)-rounded, layout [j][dv]

// ---------------- helpers ---------------------------------------------------
__device__ __forceinline__ float tf32r(float x) {
    uint32_t u;
    asm("cvt.rna.tf32.f32 %0, %1;" : "=r"(u) : "f"(x));
    return __uint_as_float(u);
}
#define CPA16(dst, src)  asm volatile("cp.async.cg.shared.global [%0], [%1], 16;" :: "r"(dst), "l"(src))
#define CPA_COMMIT()     asm volatile("cp.async.commit_group;")
#define CPA_WAIT0()      asm volatile("cp.async.wait_group 0;")
#define CPA_WAIT1()      asm volatile("cp.async.wait_group 1;")

__device__ __forceinline__ uint32_t smem_u32(const void* p) {
    uint32_t a;
    asm("{ .reg .u64 t; cvta.to.shared.u64 t, %1; cvt.u32.u64 %0, t; }" : "=r"(a) : "l"(p));
    return a;
}

// mma.sync m16n8k8 tf32 (sm_80+ baseline; works on plain sm_103 target)
__device__ __forceinline__ void mma8(float* c, const uint32_t* a, uint32_t b0, uint32_t b1) {
    asm volatile(
        "mma.sync.aligned.m16n8k8.row.col.f32.tf32.tf32.f32 "
        "{%0,%1,%2,%3}, {%4,%5,%6,%7}, {%8,%9}, {%0,%1,%2,%3};"
        : "+f"(c[0]), "+f"(c[1]), "+f"(c[2]), "+f"(c[3])
        : "r"(a[0]), "r"(a[1]), "r"(a[2]), "r"(a[3]), "r"(b0), "r"(b1));
}

// ---------------- threefry2x32, key=(0,42), partitionable ------------------
__device__ __forceinline__ uint2 tf2x32(uint32_t x0, uint32_t x1) {
    const uint32_t K1 = 42u;
    const uint32_t K2 = 0x1BD11BDAu ^ 42u;
#define TFR(r) { x0 += x1; x1 = __funnelshift_l(x1, x1, (r)); x1 ^= x0; }
    x1 += K1;
    TFR(13) TFR(15) TFR(26) TFR(6)
    x0 += K1; x1 += K2 + 1u;
    TFR(17) TFR(29) TFR(16) TFR(24)
    x0 += K2; x1 += 0u + 2u;
    TFR(13) TFR(15) TFR(26) TFR(6)
    x1 += K1 + 3u;
    TFR(17) TFR(29) TFR(16) TFR(24)
    x0 += K1; x1 += K2 + 4u;
    TFR(13) TFR(15) TFR(26) TFR(6)
    x0 += K2; x1 += 0u + 5u;
#undef TFR
    return make_uint2(x0, x1);
}
__device__ __forceinline__ bool keep_mask(uint32_t f) {
    uint2 r = tf2x32(0u, f);
    uint32_t bits = r.x ^ r.y;
    float u = __uint_as_float((bits >> 9) | 0x3F800000u) - 1.0f;
    return u < 0.75f;
}

// ---------------------------------------------------------------------------
// Kernel 1: K'[d][s] = (m @ n^T)[d][s] / 64
// ---------------------------------------------------------------------------
__global__ void k_build_kt(const float* __restrict__ m, const float* __restrict__ n) {
    __shared__ float sn[DVDIM];
    const int s = blockIdx.x;
    const float4* n4 = reinterpret_cast<const float4*>(n + (size_t)s * DVDIM);
    float4* sn4 = reinterpret_cast<float4*>(sn);
    for (int c = threadIdx.x; c < DVDIM / 4; c += blockDim.x) sn4[c] = n4[c];
    __syncthreads();
    const int d = threadIdx.x;  // blockDim = 64
    const float* mr = m + (size_t)d * DVDIM;
    float acc = 0.f;
#pragma unroll 8
    for (int c = 0; c < DVDIM; ++c) acc += mr[c] * sn[c];
    g_Kt[d * SDIM + s] = acc * (1.0f / 64.0f);
}

// ---------------------------------------------------------------------------
// Kernel 2: g_Vr = tf32(rna) round of q (elementwise, same layout)
// ---------------------------------------------------------------------------
__global__ void k_vr(const float* __restrict__ q) {
    const int idx = blockIdx.x * 256 + threadIdx.x;   // float4 index
    float4 v = reinterpret_cast<const float4*>(q)[idx];
    v.x = tf32r(v.x); v.y = tf32r(v.y); v.z = tf32r(v.z); v.w = tf32r(v.w);
    reinterpret_cast<float4*>(g_Vr)[idx] = v;
}

// ---------------------------------------------------------------------------
// Kernel 3: fused attention. QK fp32 on cores, softmax(no-max)+threefry
// dropout, PV on tensor cores (mma.sync tf32). O in registers (64/thread).
//   grid = 512 (16 b x 32 qblk), 512 threads.
// smem (bytes):
//   OFF_LF 0      : l_final[64]                (256)
//   OFF_Q  256    : sQt[d][r] 64x64 f32        (16384)
//   OFF_K  16640  : sKt[d][j] 64x64 f32        (16384)
//   OFF_P  33024  : sP [64 rows][68 stride]    (17408)
//   OFF_V  50432  : sV [64 j][520 stride]      (133120)  -> total 183552
// ---------------------------------------------------------------------------
#define OFF_LF 0
#define OFF_Q  256
#define OFF_K  16640
#define OFF_P  33024
#define OFF_V  50432
#define ATT_SMEM 183552
#define PSTR 68
#define VSTR 520

__global__ __launch_bounds__(NT, 1) void k_attn(
    const float* __restrict__ x1, float* __restrict__ out) {
    extern __shared__ char smem[];
    const uint32_t sb = smem_u32(smem);
    float* lf  = reinterpret_cast<float*>(smem + OFF_LF);
    float* sQt = reinterpret_cast<float*>(smem + OFF_Q);
    float* sK  = reinterpret_cast<float*>(smem + OFF_K);
    float* sP  = reinterpret_cast<float*>(smem + OFF_P);
    float* sV  = reinterpret_cast<float*>(smem + OFF_V);

    const int t = threadIdx.x, w = t >> 5, lane = t & 31;
    const int b = blockIdx.x >> 5;
    const int i0 = (blockIdx.x & 31) << 6;

    // ---- load Q transposed: sQt[d*64 + r] = x1[b][i0+r][d] ----
    {
        const float* xq = x1 + ((size_t)b * SDIM + i0) * DDIM;
#pragma unroll
        for (int u = 0; u < 2; ++u) {
            int idx = t + u * NT;              // 1024 float4 total
            int r = idx >> 4, d4 = (idx & 15) << 2;
            float4 v = *reinterpret_cast<const float4*>(xq + (size_t)r * DDIM + d4);
            sQt[(d4 + 0) * 64 + r] = v.x;
            sQt[(d4 + 1) * 64 + r] = v.y;
            sQt[(d4 + 2) * 64 + r] = v.z;
            sQt[(d4 + 3) * 64 + r] = v.w;
        }
    }

    // QK mapping: thread -> row t>>3, cols (t&7)*8 .. +7
    const int row = t >> 3, jg = t & 7;
    // PV mapping: warp w -> cols w*32..+31, all 64 rows
    const int g = lane >> 2, tid = lane & 3;
    const int colbase = w * 32;

    float acc[4][4][4];                         // [rowtile][coltile][frag]
#pragma unroll
    for (int rt = 0; rt < 4; ++rt)
#pragma unroll
        for (int ct = 0; ct < 4; ++ct)
#pragma unroll
            for (int k = 0; k < 4; ++k) acc[rt][ct][k] = 0.f;

    float l_acc = 0.f;
    const float inv_keep = 1.0f / 0.75f;
    const uint32_t fbase = ((uint32_t)b << 22) | ((uint32_t)(i0 + row) << 11);

    __syncthreads();

    for (int tile = 0; tile < SDIM / JT; ++tile) {
        const int j0 = tile * JT;

        // ---- cp.async K tile (group A) then V tile (group B) ----
#pragma unroll
        for (int u = 0; u < 2; ++u) {
            int idx = t + u * NT;              // 1024 float4
            int d = idx >> 4, c4 = idx & 15;
            CPA16(sb + OFF_K + (uint32_t)((d * 64 + c4 * 4) * 4),
                  g_Kt + (size_t)d * SDIM + j0 + c4 * 4);
        }
        CPA_COMMIT();
#pragma unroll
        for (int u = 0; u < 16; ++u) {
            int idx = t + u * NT;              // 8192 float4
            int jr = idx >> 7, c4 = idx & 127;
            CPA16(sb + OFF_V + (uint32_t)((jr * VSTR + c4 * 4) * 4),
                  g_Vr + (size_t)(j0 + jr) * DVDIM + c4 * 4);
        }
        CPA_COMMIT();
        CPA_WAIT1();                           // K arrived (V may still be in flight)
        __syncthreads();

        // ---- QK on cores: scores for (row, jg*8..+7) ----
        float a8[8];
#pragma unroll
        for (int u = 0; u < 8; ++u) a8[u] = 0.f;
#pragma unroll 8
        for (int d = 0; d < DDIM; ++d) {
            float qv = sQt[d * 64 + row];
            const float* kr = sK + d * 64 + jg * 8;
            float4 ka = *reinterpret_cast<const float4*>(kr);
            float4 kb = *reinterpret_cast<const float4*>(kr + 4);
            a8[0] += qv * ka.x; a8[1] += qv * ka.y; a8[2] += qv * ka.z; a8[3] += qv * ka.w;
            a8[4] += qv * kb.x; a8[5] += qv * kb.y; a8[6] += qv * kb.z; a8[7] += qv * kb.w;
        }

        // ---- exp (no max needed: |s| <~ 18), l-sum, threefry dropout ----
        float l0 = 0.f;
        float pv[8];
        const uint32_t fb = fbase | (uint32_t)(j0 + jg * 8);
#pragma unroll
        for (int u = 0; u < 8; ++u) {
            float p = __expf(a8[u]);
            l0 += p;
            pv[u] = keep_mask(fb + u) ? tf32r(p * inv_keep) : 0.f;
        }
#pragma unroll
        for (int mask = 1; mask < 8; mask <<= 1)
            l0 += __shfl_xor_sync(0xffffffffu, l0, mask);
        if (jg == 0) l_acc += l0;

        // ---- write P tile (tf32-rounded, stride 68) ----
        *reinterpret_cast<float4*>(sP + row * PSTR + jg * 8) =
            make_float4(pv[0], pv[1], pv[2], pv[3]);
        *reinterpret_cast<float4*>(sP + row * PSTR + jg * 8 + 4) =
            make_float4(pv[4], pv[5], pv[6], pv[7]);

        CPA_WAIT0();                           // V arrived
        __syncthreads();

        // ---- PV on tensor cores: O[64 x 512] += P[64 x 64] @ V[64 x 512] ----
#pragma unroll
        for (int ks = 0; ks < 8; ++ks) {
            const int k0 = ks * 8;
            uint32_t af[4][4];
#pragma unroll
            for (int rt = 0; rt < 4; ++rt) {
                const float* pb = sP + (rt * 16 + g) * PSTR + k0 + tid;
                af[rt][0] = __float_as_uint(pb[0]);
                af[rt][1] = __float_as_uint(pb[8 * PSTR]);
                af[rt][2] = __float_as_uint(pb[4]);
                af[rt][3] = __float_as_uint(pb[8 * PSTR + 4]);
            }
#pragma unroll
            for (int ct = 0; ct < 4; ++ct) {
                const int c = colbase + ct * 8 + g;
                uint32_t b0 = __float_as_uint(sV[(k0 + tid) * VSTR + c]);
                uint32_t b1 = __float_as_uint(sV[(k0 + tid + 4) * VSTR + c]);
#pragma unroll
                for (int rt = 0; rt < 4; ++rt)
                    mma8(acc[rt][ct], af[rt], b0, b1);
            }
        }
        __syncthreads();                       // done reading sK/sV/sP this tile
    }

    // ---- epilogue: l to smem, then normalized stores ----
    if (jg == 0) lf[row] = l_acc;
    __syncthreads();

#pragma unroll
    for (int rt = 0; rt < 4; ++rt) {
        const int r0 = rt * 16 + g;
        const float inv0 = 1.0f / lf[r0];
        const float inv1 = 1.0f / lf[r0 + 8];
        float* o0 = out + ((size_t)(b * SDIM + i0 + r0)) * DVDIM;
        float* o1 = out + ((size_t)(b * SDIM + i0 + r0 + 8)) * DVDIM;
#pragma unroll
        for (int ct = 0; ct < 4; ++ct) {
            const int c = colbase + ct * 8 + tid * 2;
            float2 v0 = make_float2(acc[rt][ct][0] * inv0, acc[rt][ct][1] * inv0);
            float2 v1 = make_float2(acc[rt][ct][2] * inv1, acc[rt][ct][3] * inv1);
            *reinterpret_cast<float2*>(o0 + c) = v0;
            *reinterpret_cast<float2*>(o1 + c) = v1;
        }
    }
}

// ---------------------------------------------------------------------------
extern "C" void kernel_launch(void* const* d_in, const int* in_sizes, int n_in,
                              void* d_out, int out_size) {
    const float* x1 = (const float*)d_in[0];  // [16,2048,64]
    const float* m  = (const float*)d_in[1];  // [64,512]
    const float* n  = (const float*)d_in[2];  // [2048,512]
    const float* q  = (const float*)d_in[3];  // [2048,512]
    float* out = (float*)d_out;               // [16,2048,512]

    cudaFuncSetAttribute(k_attn, cudaFuncAttributeMaxDynamicSharedMemorySize, ATT_SMEM);

    k_build_kt<<<SDIM, DDIM>>>(m, n);
    k_vr<<<SDIM * DVDIM / 1024, 256>>>(q);
    k_attn<<<BDIM * (SDIM / QB), NT, ATT_SMEM>>>(x1, out);
}

// round 11
// speedup vs baseline: 3.1020x; 2.1278x over previous
#include <cuda_runtime.h>
#include <cstdint>

#define SDIM 2048
#define BDIM 16
#define DDIM 64
#define DVDIM 512
#define QB 64
#define JT 64
#define NT 512

// ---------------- scratch ---------------------------------------------------
__device__ float g_Kth[DDIM * SDIM];     // tf32 hi of (m@n^T)/64, [d][s]
__device__ float g_Ktl[DDIM * SDIM];     // tf32 lo
__device__ float g_Vr[SDIM * DVDIM];     // V tf32-rounded, [j][dv]

// ---------------- helpers ---------------------------------------------------
__device__ __forceinline__ float tf32r(float x) {
    uint32_t u;
    asm("cvt.rna.tf32.f32 %0, %1;" : "=r"(u) : "f"(x));
    return __uint_as_float(u);
}
#define CPA16(dst, src)  asm volatile("cp.async.cg.shared.global [%0], [%1], 16;" :: "r"(dst), "l"(src))
#define CPA_COMMIT()     asm volatile("cp.async.commit_group;")
#define CPA_WAIT0()      asm volatile("cp.async.wait_group 0;")
#define CPA_WAIT1()      asm volatile("cp.async.wait_group 1;")

__device__ __forceinline__ uint32_t smem_u32(const void* p) {
    uint32_t a;
    asm("{ .reg .u64 t; cvta.to.shared.u64 t, %1; cvt.u32.u64 %0, t; }" : "=r"(a) : "l"(p));
    return a;
}
__device__ __forceinline__ void mma8(float* c, const uint32_t* a, uint32_t b0, uint32_t b1) {
    asm volatile(
        "mma.sync.aligned.m16n8k8.row.col.f32.tf32.tf32.f32 "
        "{%0,%1,%2,%3}, {%4,%5,%6,%7}, {%8,%9}, {%0,%1,%2,%3};"
        : "+f"(c[0]), "+f"(c[1]), "+f"(c[2]), "+f"(c[3])
        : "r"(a[0]), "r"(a[1]), "r"(a[2]), "r"(a[3]), "r"(b0), "r"(b1));
}

// ---------------- threefry2x32, key=(0,42), partitionable ------------------
__device__ __forceinline__ uint2 tf2x32(uint32_t x0, uint32_t x1) {
    const uint32_t K1 = 42u;
    const uint32_t K2 = 0x1BD11BDAu ^ 42u;
#define TFR(r) { x0 += x1; x1 = __funnelshift_l(x1, x1, (r)); x1 ^= x0; }
    x1 += K1;
    TFR(13) TFR(15) TFR(26) TFR(6)
    x0 += K1; x1 += K2 + 1u;
    TFR(17) TFR(29) TFR(16) TFR(24)
    x0 += K2; x1 += 0u + 2u;
    TFR(13) TFR(15) TFR(26) TFR(6)
    x1 += K1 + 3u;
    TFR(17) TFR(29) TFR(16) TFR(24)
    x0 += K1; x1 += K2 + 4u;
    TFR(13) TFR(15) TFR(26) TFR(6)
    x0 += K2; x1 += 0u + 5u;
#undef TFR
    return make_uint2(x0, x1);
}
__device__ __forceinline__ bool keep_mask(uint32_t f) {
    uint2 r = tf2x32(0u, f);
    uint32_t bits = r.x ^ r.y;
    float u = __uint_as_float((bits >> 9) | 0x3F800000u) - 1.0f;
    return u < 0.75f;
}

// ---------------------------------------------------------------------------
// Kernel 1: tiled GEMM K' = (m @ n^T)/64, split tf32 hi/lo -> g_Kth/g_Ktl
//   grid 32 (s-blocks of 64), 256 threads, 4x4 micro-tiles
//   NOTE: smem row stride 68 floats = 272 B (16B multiple) for float4 stores
// ---------------------------------------------------------------------------
__global__ __launch_bounds__(256) void k_build_kt(
    const float* __restrict__ m, const float* __restrict__ n) {
    __shared__ float smm[64][68];   // m[d][c-chunk]
    __shared__ float snn[64][68];   // n[s][c-chunk]
    const int t = threadIdx.x;
    const int s0 = blockIdx.x * 64;
    const int di = (t & 15) * 4, sj = (t >> 4) * 4;
    float acc[4][4] = {};
    for (int c0 = 0; c0 < DVDIM; c0 += 64) {
#pragma unroll
        for (int u = 0; u < 4; ++u) {
            int idx = t + u * 256;
            int r = idx >> 4, c4 = (idx & 15) * 4;
            *reinterpret_cast<float4*>(&smm[r][c4]) =
                *reinterpret_cast<const float4*>(m + (size_t)r * DVDIM + c0 + c4);
            *reinterpret_cast<float4*>(&snn[r][c4]) =
                *reinterpret_cast<const float4*>(n + (size_t)(s0 + r) * DVDIM + c0 + c4);
        }
        __syncthreads();
#pragma unroll 8
        for (int c = 0; c < 64; ++c) {
            float mv0 = smm[di][c], mv1 = smm[di + 1][c], mv2 = smm[di + 2][c], mv3 = smm[di + 3][c];
            float nv0 = snn[sj][c], nv1 = snn[sj + 1][c], nv2 = snn[sj + 2][c], nv3 = snn[sj + 3][c];
            acc[0][0] += mv0 * nv0; acc[0][1] += mv0 * nv1; acc[0][2] += mv0 * nv2; acc[0][3] += mv0 * nv3;
            acc[1][0] += mv1 * nv0; acc[1][1] += mv1 * nv1; acc[1][2] += mv1 * nv2; acc[1][3] += mv1 * nv3;
            acc[2][0] += mv2 * nv0; acc[2][1] += mv2 * nv1; acc[2][2] += mv2 * nv2; acc[2][3] += mv2 * nv3;
            acc[3][0] += mv3 * nv0; acc[3][1] += mv3 * nv1; acc[3][2] += mv3 * nv2; acc[3][3] += mv3 * nv3;
        }
        __syncthreads();
    }
#pragma unroll
    for (int i = 0; i < 4; ++i)
#pragma unroll
        for (int j = 0; j < 4; ++j) {
            float val = acc[i][j] * (1.0f / 64.0f);
            float hi = tf32r(val);
            g_Kth[(size_t)(di + i) * SDIM + s0 + sj + j] = hi;
            g_Ktl[(size_t)(di + i) * SDIM + s0 + sj + j] = tf32r(val - hi);
        }
}

// ---------------------------------------------------------------------------
// Kernel 2: g_Vr = tf32(rna) of q
// ---------------------------------------------------------------------------
__global__ void k_vr(const float* __restrict__ q) {
    const int idx = blockIdx.x * 256 + threadIdx.x;
    float4 v = reinterpret_cast<const float4*>(q)[idx];
    v.x = tf32r(v.x); v.y = tf32r(v.y); v.z = tf32r(v.z); v.w = tf32r(v.w);
    reinterpret_cast<float4*>(g_Vr)[idx] = v;
}

// ---------------------------------------------------------------------------
// Kernel 3: fused attention, both GEMMs on tensor cores.
//   QK: split-tf32 (hi/lo) mma. PV: tf32 mma. grid 512, 512 threads.
// smem (bytes):
//   OFF_LF 0      lf[64]                  256
//   OFF_LP 256    lpart[4][64]            1024
//   OFF_QH 1280   sQh [64][68]            17408
//   OFF_QL 18688  sQl [64][68]            17408
//   OFF_KH 36096  sKh [64][72]            18432
//   OFF_KL 54528  sKl [64][72]            18432
//   OFF_P  72960  sP  [64][68]            17408
//   OFF_V  90368  sV  [64][520]           133120   total 223488
// ---------------------------------------------------------------------------
#define OFF_LF 0
#define OFF_LP 256
#define OFF_QH 1280
#define OFF_QL 18688
#define OFF_KH 36096
#define OFF_KL 54528
#define OFF_P  72960
#define OFF_V  90368
#define ATT_SMEM 223488
#define QSTR 68
#define KSTR 72
#define PSTR 68
#define VSTR 520

__global__ __launch_bounds__(NT, 1) void k_attn(
    const float* __restrict__ x1, float* __restrict__ out) {
    extern __shared__ char smem[];
    const uint32_t sb = smem_u32(smem);
    float* lf    = reinterpret_cast<float*>(smem + OFF_LF);
    float* lpart = reinterpret_cast<float*>(smem + OFF_LP);
    float* sQh   = reinterpret_cast<float*>(smem + OFF_QH);
    float* sQl   = reinterpret_cast<float*>(smem + OFF_QL);
    float* sKh   = reinterpret_cast<float*>(smem + OFF_KH);
    float* sKl   = reinterpret_cast<float*>(smem + OFF_KL);
    float* sP    = reinterpret_cast<float*>(smem + OFF_P);
    float* sV    = reinterpret_cast<float*>(smem + OFF_V);

    const int t = threadIdx.x, w = t >> 5, lane = t & 31;
    const int g = lane >> 2, tid = lane & 3;
    const int b = blockIdx.x >> 5;
    const int i0 = (blockIdx.x & 31) << 6;

    if (t < 256) lpart[t] = 0.f;

    // ---- load Q, split tf32 hi/lo, row-major [r][d] ----
    {
        const float* xq = x1 + ((size_t)b * SDIM + i0) * DDIM;
#pragma unroll
        for (int u = 0; u < 2; ++u) {
            int idx = t + u * NT;
            int r = idx >> 4, d4 = (idx & 15) << 2;
            float4 v = *reinterpret_cast<const float4*>(xq + (size_t)r * DDIM + d4);
            float4 h, l;
            h.x = tf32r(v.x); l.x = tf32r(v.x - h.x);
            h.y = tf32r(v.y); l.y = tf32r(v.y - h.y);
            h.z = tf32r(v.z); l.z = tf32r(v.z - h.z);
            h.w = tf32r(v.w); l.w = tf32r(v.w - h.w);
            *reinterpret_cast<float4*>(sQh + r * QSTR + d4) = h;
            *reinterpret_cast<float4*>(sQl + r * QSTR + d4) = l;
        }
    }
    __syncthreads();

    // QK warp mapping: mtile = w&3 (rows), wc = w>>2 (16-col group, 2 n8 units)
    const int mtile = w & 3, wc = w >> 2;
    const int m0 = mtile * 16, n0 = wc * 16;
    // PV mapping: warp -> 32 cols
    const int colbase = w * 32;

    float acc[4][4][4];
#pragma unroll
    for (int rt = 0; rt < 4; ++rt)
#pragma unroll
        for (int ct = 0; ct < 4; ++ct)
#pragma unroll
            for (int k = 0; k < 4; ++k) acc[rt][ct][k] = 0.f;

    const float inv_keep = 1.0f / 0.75f;
    const uint32_t frow_g  = ((uint32_t)b << 22) | ((uint32_t)(i0 + m0 + g) << 11);
    const uint32_t frow_g8 = frow_g + (8u << 11);

    for (int tile = 0; tile < SDIM / JT; ++tile) {
        const int j0 = tile * JT;

        // ---- cp.async K hi/lo (group A), V (group B) ----
#pragma unroll
        for (int u = 0; u < 2; ++u) {
            int idx = t + u * NT;
            int d = idx >> 4, c4 = (idx & 15) << 2;
            CPA16(sb + OFF_KH + (uint32_t)((d * KSTR + c4) * 4),
                  g_Kth + (size_t)d * SDIM + j0 + c4);
            CPA16(sb + OFF_KL + (uint32_t)((d * KSTR + c4) * 4),
                  g_Ktl + (size_t)d * SDIM + j0 + c4);
        }
        CPA_COMMIT();
#pragma unroll
        for (int u = 0; u < 16; ++u) {
            int idx = t + u * NT;
            int jr = idx >> 7, c4 = (idx & 127) << 2;
            CPA16(sb + OFF_V + (uint32_t)((jr * VSTR + c4) * 4),
                  g_Vr + (size_t)(j0 + jr) * DVDIM + c4);
        }
        CPA_COMMIT();
        CPA_WAIT1();
        __syncthreads();

        // ---- QK on tensor cores: split tf32 (hh + hl + lh) ----
        float cfr[2][4] = {{0.f, 0.f, 0.f, 0.f}, {0.f, 0.f, 0.f, 0.f}};
#pragma unroll
        for (int ks = 0; ks < 8; ++ks) {
            const int k0 = ks * 8;
            uint32_t ah[4], al[4];
            const float* qh = sQh + (m0 + g) * QSTR + k0 + tid;
            const float* ql = sQl + (m0 + g) * QSTR + k0 + tid;
            ah[0] = __float_as_uint(qh[0]);
            ah[1] = __float_as_uint(qh[8 * QSTR]);
            ah[2] = __float_as_uint(qh[4]);
            ah[3] = __float_as_uint(qh[8 * QSTR + 4]);
            al[0] = __float_as_uint(ql[0]);
            al[1] = __float_as_uint(ql[8 * QSTR]);
            al[2] = __float_as_uint(ql[4]);
            al[3] = __float_as_uint(ql[8 * QSTR + 4]);
#pragma unroll
            for (int u = 0; u < 2; ++u) {
                const int c = n0 + u * 8 + g;          // B-frag col
                uint32_t bh0 = __float_as_uint(sKh[(k0 + tid) * KSTR + c]);
                uint32_t bh1 = __float_as_uint(sKh[(k0 + tid + 4) * KSTR + c]);
                uint32_t bl0 = __float_as_uint(sKl[(k0 + tid) * KSTR + c]);
                uint32_t bl1 = __float_as_uint(sKl[(k0 + tid + 4) * KSTR + c]);
                mma8(cfr[u], ah, bh0, bh1);
                mma8(cfr[u], ah, bl0, bl1);
                mma8(cfr[u], al, bh0, bh1);
            }
        }

        // ---- exp, dropout, l partial sums (C layout: rows m0+g/m0+g+8, cols n0+u*8+2tid) ----
        float lg = 0.f, lg8 = 0.f;
        float pvv[2][4];
#pragma unroll
        for (int u = 0; u < 2; ++u) {
            const uint32_t col = (uint32_t)(j0 + n0 + u * 8 + 2 * tid);
            float p0 = __expf(cfr[u][0]);
            float p1 = __expf(cfr[u][1]);
            float p2 = __expf(cfr[u][2]);
            float p3 = __expf(cfr[u][3]);
            lg += p0 + p1;
            lg8 += p2 + p3;
            pvv[u][0] = keep_mask(frow_g  | col)        ? tf32r(p0 * inv_keep) : 0.f;
            pvv[u][1] = keep_mask(frow_g  | (col + 1))  ? tf32r(p1 * inv_keep) : 0.f;
            pvv[u][2] = keep_mask(frow_g8 | col)        ? tf32r(p2 * inv_keep) : 0.f;
            pvv[u][3] = keep_mask(frow_g8 | (col + 1))  ? tf32r(p3 * inv_keep) : 0.f;
        }
        // reduce over tid quad (lanes g*4..g*4+3)
        lg  += __shfl_xor_sync(0xffffffffu, lg, 1);
        lg  += __shfl_xor_sync(0xffffffffu, lg, 2);
        lg8 += __shfl_xor_sync(0xffffffffu, lg8, 1);
        lg8 += __shfl_xor_sync(0xffffffffu, lg8, 2);
        if (tid == 0) {
            lpart[wc * 64 + m0 + g]     += lg;
            lpart[wc * 64 + m0 + 8 + g] += lg8;
        }

        // ---- write P (dropped, tf32-rounded) ----
#pragma unroll
        for (int u = 0; u < 2; ++u) {
            float* pb = sP + (m0 + g) * PSTR + n0 + u * 8 + 2 * tid;
            pb[0] = pvv[u][0];
            pb[1] = pvv[u][1];
            pb[8 * PSTR] = pvv[u][2];
            pb[8 * PSTR + 1] = pvv[u][3];
        }

        CPA_WAIT0();          // V arrived
        __syncthreads();      // P visible to all warps

        // ---- PV on tensor cores ----
#pragma unroll
        for (int ks = 0; ks < 8; ++ks) {
            const int k0 = ks * 8;
            uint32_t af[4][4];
#pragma unroll
            for (int rt = 0; rt < 4; ++rt) {
                const float* pb = sP + (rt * 16 + g) * PSTR + k0 + tid;
                af[rt][0] = __float_as_uint(pb[0]);
                af[rt][1] = __float_as_uint(pb[8 * PSTR]);
                af[rt][2] = __float_as_uint(pb[4]);
                af[rt][3] = __float_as_uint(pb[8 * PSTR + 4]);
            }
#pragma unroll
            for (int ct = 0; ct < 4; ++ct) {
                const int c = colbase + ct * 8 + g;
                uint32_t b0 = __float_as_uint(sV[(k0 + tid) * VSTR + c]);
                uint32_t b1 = __float_as_uint(sV[(k0 + tid + 4) * VSTR + c]);
#pragma unroll
                for (int rt = 0; rt < 4; ++rt)
                    mma8(acc[rt][ct], af[rt], b0, b1);
            }
        }
        __syncthreads();      // done reading sK/sV/sP before next tile's cp.async
    }

    // ---- epilogue ----
    if (t < 64) lf[t] = lpart[t] + lpart[64 + t] + lpart[128 + t] + lpart[192 + t];
    __syncthreads();

#pragma unroll
    for (int rt = 0; rt < 4; ++rt) {
        const int r0 = rt * 16 + g;
        const float inv0 = 1.0f / lf[r0];
        const float inv1 = 1.0f / lf[r0 + 8];
        float* o0 = out + ((size_t)(b * SDIM + i0 + r0)) * DVDIM;
        float* o1 = out + ((size_t)(b * SDIM + i0 + r0 + 8)) * DVDIM;
#pragma unroll
        for (int ct = 0; ct < 4; ++ct) {
            const int c = colbase + ct * 8 + tid * 2;
            *reinterpret_cast<float2*>(o0 + c) =
                make_float2(acc[rt][ct][0] * inv0, acc[rt][ct][1] * inv0);
            *reinterpret_cast<float2*>(o1 + c) =
                make_float2(acc[rt][ct][2] * inv1, acc[rt][ct][3] * inv1);
        }
    }
}

// ---------------------------------------------------------------------------
extern "C" void kernel_launch(void* const* d_in, const int* in_sizes, int n_in,
                              void* d_out, int out_size) {
    const float* x1 = (const float*)d_in[0];  // [16,2048,64]
    const float* m  = (const float*)d_in[1];  // [64,512]
    const float* n  = (const float*)d_in[2];  // [2048,512]
    const float* q  = (const float*)d_in[3];  // [2048,512]
    float* out = (float*)d_out;               // [16,2048,512]

    cudaFuncSetAttribute(k_attn, cudaFuncAttributeMaxDynamicSharedMemorySize, ATT_SMEM);

    k_build_kt<<<SDIM / 64, 256>>>(m, n);
    k_vr<<<SDIM * DVDIM / 1024, 256>>>(q);
    k_attn<<<BDIM * (SDIM / QB), NT, ATT_SMEM>>>(x1, out);
}

// round 12
// speedup vs baseline: 5.1039x; 1.6454x over previous
#include <cuda_runtime.h>
#include <cuda_fp16.h>
#include <cstdint>

#define SDIM 2048
#define BDIM 16
#define DDIM 64
#define DVDIM 512
#define QB 64
#define JT 64
#define NT 512

// ---------------- scratch ---------------------------------------------------
__device__ __half g_Kth[DDIM * SDIM];    // fp16 hi of (m@n^T)/64, [d][s]
__device__ __half g_Ktl[DDIM * SDIM];    // fp16 lo residual
__device__ __half g_Vh[SDIM * DVDIM];    // V fp16, [j][dv]

// ---------------- helpers ---------------------------------------------------
#define CPA16(dst, src)  asm volatile("cp.async.cg.shared.global [%0], [%1], 16;" :: "r"(dst), "l"(src))
#define CPA_COMMIT()     asm volatile("cp.async.commit_group;")
#define CPA_WAIT0()      asm volatile("cp.async.wait_group 0;")
#define CPA_WAIT1()      asm volatile("cp.async.wait_group 1;")

__device__ __forceinline__ uint32_t smem_u32(const void* p) {
    uint32_t a;
    asm("{ .reg .u64 t; cvta.to.shared.u64 t, %1; cvt.u32.u64 %0, t; }" : "=r"(a) : "l"(p));
    return a;
}
__device__ __forceinline__ void ldsm4(uint32_t* r, uint32_t addr) {
    asm volatile("ldmatrix.sync.aligned.m8n8.x4.shared.b16 {%0,%1,%2,%3}, [%4];"
        : "=r"(r[0]), "=r"(r[1]), "=r"(r[2]), "=r"(r[3]) : "r"(addr));
}
__device__ __forceinline__ void ldsm4t(uint32_t* r, uint32_t addr) {
    asm volatile("ldmatrix.sync.aligned.m8n8.x4.trans.shared.b16 {%0,%1,%2,%3}, [%4];"
        : "=r"(r[0]), "=r"(r[1]), "=r"(r[2]), "=r"(r[3]) : "r"(addr));
}
__device__ __forceinline__ void mma16(float* c, const uint32_t* a, uint32_t b0, uint32_t b1) {
    asm volatile("mma.sync.aligned.m16n8k16.row.col.f32.f16.f16.f32 "
        "{%0,%1,%2,%3}, {%4,%5,%6,%7}, {%8,%9}, {%0,%1,%2,%3};"
        : "+f"(c[0]), "+f"(c[1]), "+f"(c[2]), "+f"(c[3])
        : "r"(a[0]), "r"(a[1]), "r"(a[2]), "r"(a[3]), "r"(b0), "r"(b1));
}

// ---------------- threefry2x32, key=(0,42), partitionable ------------------
__device__ __forceinline__ uint2 tf2x32(uint32_t x0, uint32_t x1) {
    const uint32_t K1 = 42u;
    const uint32_t K2 = 0x1BD11BDAu ^ 42u;
#define TFR(r) { x0 += x1; x1 = __funnelshift_l(x1, x1, (r)); x1 ^= x0; }
    x1 += K1;
    TFR(13) TFR(15) TFR(26) TFR(6)
    x0 += K1; x1 += K2 + 1u;
    TFR(17) TFR(29) TFR(16) TFR(24)
    x0 += K2; x1 += 0u + 2u;
    TFR(13) TFR(15) TFR(26) TFR(6)
    x1 += K1 + 3u;
    TFR(17) TFR(29) TFR(16) TFR(24)
    x0 += K1; x1 += K2 + 4u;
    TFR(13) TFR(15) TFR(26) TFR(6)
    x0 += K2; x1 += 0u + 5u;
#undef TFR
    return make_uint2(x0, x1);
}
__device__ __forceinline__ bool keep_mask(uint32_t f) {
    uint2 r = tf2x32(0u, f);
    uint32_t bits = r.x ^ r.y;
    float u = __uint_as_float((bits >> 9) | 0x3F800000u) - 1.0f;
    return u < 0.75f;
}

// ---------------------------------------------------------------------------
// Kernel 1: K' = (m @ n^T)/64, fp16 hi/lo. grid 128 (s-blocks of 16), 256 thr
// ---------------------------------------------------------------------------
__global__ __launch_bounds__(256) void k_build_kt(
    const float* __restrict__ m, const float* __restrict__ n) {
    __shared__ float smm[64][68];
    __shared__ float snn[16][68];
    const int t = threadIdx.x;
    const int s0 = blockIdx.x * 16;
    const int di = (t & 15) * 4, sj = t >> 4;
    float acc[4] = {};
    for (int c0 = 0; c0 < DVDIM; c0 += 64) {
#pragma unroll
        for (int u = 0; u < 4; ++u) {
            int idx = t + u * 256;
            int r = idx >> 4, c4 = (idx & 15) * 4;
            *reinterpret_cast<float4*>(&smm[r][c4]) =
                *reinterpret_cast<const float4*>(m + (size_t)r * DVDIM + c0 + c4);
        }
        {
            int r = t >> 4, c4 = (t & 15) * 4;
            *reinterpret_cast<float4*>(&snn[r][c4]) =
                *reinterpret_cast<const float4*>(n + (size_t)(s0 + r) * DVDIM + c0 + c4);
        }
        __syncthreads();
#pragma unroll 8
        for (int c = 0; c < 64; ++c) {
            float nv = snn[sj][c];
            acc[0] += smm[di][c] * nv;
            acc[1] += smm[di + 1][c] * nv;
            acc[2] += smm[di + 2][c] * nv;
            acc[3] += smm[di + 3][c] * nv;
        }
        __syncthreads();
    }
#pragma unroll
    for (int i = 0; i < 4; ++i) {
        float val = acc[i] * (1.0f / 64.0f);
        __half hh = __float2half_rn(val);
        g_Kth[(size_t)(di + i) * SDIM + s0 + sj] = hh;
        g_Ktl[(size_t)(di + i) * SDIM + s0 + sj] = __float2half_rn(val - __half2float(hh));
    }
}

// ---------------------------------------------------------------------------
// Kernel 2: g_Vh = fp16(q)
// ---------------------------------------------------------------------------
__global__ void k_vr(const float* __restrict__ q) {
    const int idx = blockIdx.x * 256 + threadIdx.x;
    float4 v = reinterpret_cast<const float4*>(q)[idx];
    __half2* dst = reinterpret_cast<__half2*>(g_Vh) + idx * 2;
    dst[0] = __floats2half2_rn(v.x, v.y);
    dst[1] = __floats2half2_rn(v.z, v.w);
}

// ---------------------------------------------------------------------------
// Kernel 3: fused attention, all-fp16 operands on tensor cores (m16n8k16).
//   QK: fp16 hi/lo split (hh+hl+lh). PV: fp16 with P scaled by 2^-14.
//   grid 512 (16 b x 32 qblk), 512 threads.
// smem (bytes):
//   OFF_LF 0      lf[64] f32            256
//   OFF_LP 256    lpart[4][64] f32      1024
//   OFF_QH 1280   half [64][72]         9216
//   OFF_QL 10496  half [64][72]         9216
//   OFF_KH 19712  half [64][72]         9216
//   OFF_KL 28928  half [64][72]         9216
//   OFF_P  38144  half [64][72]         9216
//   OFF_V  47360  half [64][520]        66560    total 113920
// ---------------------------------------------------------------------------
#define OFF_LF 0
#define OFF_LP 256
#define OFF_QH 1280
#define OFF_QL 10496
#define OFF_KH 19712
#define OFF_KL 28928
#define OFF_P  38144
#define OFF_V  47360
#define ATT_SMEM 113920
#define HSTR 72            // halves (144 B row) for Q/K/P tiles
#define VSTRH 520          // halves (1040 B row) for V tile
#define P_SC 6.103515625e-05f   // 2^-14
#define P_UNSC 16384.0f

__global__ __launch_bounds__(NT, 1) void k_attn(
    const float* __restrict__ x1, float* __restrict__ out) {
    extern __shared__ char smem[];
    const uint32_t sb = smem_u32(smem);
    float* lf    = reinterpret_cast<float*>(smem + OFF_LF);
    float* lpart = reinterpret_cast<float*>(smem + OFF_LP);
    __half* sQh  = reinterpret_cast<__half*>(smem + OFF_QH);
    __half* sQl  = reinterpret_cast<__half*>(smem + OFF_QL);
    __half* sP   = reinterpret_cast<__half*>(smem + OFF_P);

    const int t = threadIdx.x, w = t >> 5, lane = t & 31;
    const int g = lane >> 2, tid = lane & 3;
    const int b = blockIdx.x >> 5;
    const int i0 = (blockIdx.x & 31) << 6;
    const int lrow = lane & 15;             // ldmatrix row select
    const int lcol8 = (lane >> 4) * 8;      // ldmatrix col-half select

    if (t < 256) lpart[t] = 0.f;

    // ---- load Q, split fp16 hi/lo ----
    {
        const float* xq = x1 + ((size_t)b * SDIM + i0) * DDIM;
#pragma unroll
        for (int u = 0; u < 2; ++u) {
            int idx = t + u * NT;
            int r = idx >> 4, d4 = (idx & 15) << 2;
            float4 v = *reinterpret_cast<const float4*>(xq + (size_t)r * DDIM + d4);
            __half hx = __float2half_rn(v.x), hy = __float2half_rn(v.y);
            __half hz = __float2half_rn(v.z), hw = __float2half_rn(v.w);
            __half lx = __float2half_rn(v.x - __half2float(hx));
            __half ly = __float2half_rn(v.y - __half2float(hy));
            __half lz = __float2half_rn(v.z - __half2float(hz));
            __half lw = __float2half_rn(v.w - __half2float(hw));
            *reinterpret_cast<__half2*>(sQh + r * HSTR + d4)     = __halves2half2(hx, hy);
            *reinterpret_cast<__half2*>(sQh + r * HSTR + d4 + 2) = __halves2half2(hz, hw);
            *reinterpret_cast<__half2*>(sQl + r * HSTR + d4)     = __halves2half2(lx, ly);
            *reinterpret_cast<__half2*>(sQl + r * HSTR + d4 + 2) = __halves2half2(lz, lw);
        }
    }
    __syncthreads();

    // QK warp mapping: rows m0 = (w&3)*16, cols n0 = (w>>2)*16
    const int m0 = (w & 3) * 16, n0 = (w >> 2) * 16;
    // PV mapping: warp -> 32 output cols
    const int colbase = w * 32;

    float acc[4][4][4];
#pragma unroll
    for (int rt = 0; rt < 4; ++rt)
#pragma unroll
        for (int ct = 0; ct < 4; ++ct)
#pragma unroll
            for (int k = 0; k < 4; ++k) acc[rt][ct][k] = 0.f;

    const float psc = (1.0f / 0.75f) * P_SC;
    const uint32_t frow_g  = ((uint32_t)b << 22) | ((uint32_t)(i0 + m0 + g) << 11);
    const uint32_t frow_g8 = frow_g + (8u << 11);

    for (int tile = 0; tile < SDIM / JT; ++tile) {
        const int j0 = tile * JT;

        // ---- cp.async: K hi/lo (group A, 1024 ops), V (group B, 4096 ops) ----
        {
            int d = t >> 3, c = t & 7;   // 512 threads -> 64 d-rows x 8 chunks
            uint32_t dsto = (uint32_t)(d * 144 + c * 16);
            const __half* srch = g_Kth + (size_t)d * SDIM + j0 + c * 8;
            const __half* srcl = g_Ktl + (size_t)d * SDIM + j0 + c * 8;
            CPA16(sb + OFF_KH + dsto, srch);
            CPA16(sb + OFF_KL + dsto, srcl);
        }
        CPA_COMMIT();
#pragma unroll
        for (int u = 0; u < 8; ++u) {
            int idx = t + u * NT;
            int jr = idx >> 6, c = idx & 63;
            CPA16(sb + OFF_V + (uint32_t)(jr * 1040 + c * 16),
                  g_Vh + (size_t)(j0 + jr) * DVDIM + c * 8);
        }
        CPA_COMMIT();
        CPA_WAIT1();
        __syncthreads();

        // ---- QK on tensor cores: fp16 split (hh + hl + lh), k16 steps ----
        float cfr[2][4] = {{0.f, 0.f, 0.f, 0.f}, {0.f, 0.f, 0.f, 0.f}};
#pragma unroll
        for (int ks = 0; ks < 4; ++ks) {
            const int k0 = ks * 16;
            uint32_t ah[4], al[4], bh[4], bl[4];
            uint32_t qoff = (uint32_t)((m0 + lrow) * 144 + (k0 + lcol8) * 2);
            ldsm4(ah, sb + OFF_QH + qoff);
            ldsm4(al, sb + OFF_QL + qoff);
            uint32_t koff = (uint32_t)((k0 + lrow) * 144 + (n0 + lcol8) * 2);
            ldsm4t(bh, sb + OFF_KH + koff);
            ldsm4t(bl, sb + OFF_KL + koff);
#pragma unroll
            for (int u = 0; u < 2; ++u) {
                mma16(cfr[u], ah, bh[u * 2], bh[u * 2 + 1]);
                mma16(cfr[u], ah, bl[u * 2], bl[u * 2 + 1]);
                mma16(cfr[u], al, bh[u * 2], bh[u * 2 + 1]);
            }
        }

        // ---- exp, dropout, l partials (C: rows m0+g / m0+g+8, cols n0+u*8+2tid) ----
        float lg = 0.f, lg8 = 0.f;
#pragma unroll
        for (int u = 0; u < 2; ++u) {
            const uint32_t col = (uint32_t)(j0 + n0 + u * 8 + 2 * tid);
            float p0 = __expf(cfr[u][0]);
            float p1 = __expf(cfr[u][1]);
            float p2 = __expf(cfr[u][2]);
            float p3 = __expf(cfr[u][3]);
            lg += p0 + p1;
            lg8 += p2 + p3;
            float v0 = keep_mask(frow_g  | col)       ? p0 * psc : 0.f;
            float v1 = keep_mask(frow_g  | (col + 1)) ? p1 * psc : 0.f;
            float v2 = keep_mask(frow_g8 | col)       ? p2 * psc : 0.f;
            float v3 = keep_mask(frow_g8 | (col + 1)) ? p3 * psc : 0.f;
            __half* pb = sP + (m0 + g) * HSTR + n0 + u * 8 + 2 * tid;
            *reinterpret_cast<__half2*>(pb)            = __floats2half2_rn(v0, v1);
            *reinterpret_cast<__half2*>(pb + 8 * HSTR) = __floats2half2_rn(v2, v3);
        }
        lg  += __shfl_xor_sync(0xffffffffu, lg, 1);
        lg  += __shfl_xor_sync(0xffffffffu, lg, 2);
        lg8 += __shfl_xor_sync(0xffffffffu, lg8, 1);
        lg8 += __shfl_xor_sync(0xffffffffu, lg8, 2);
        if (tid == 0) {
            const int wc = w >> 2;
            lpart[wc * 64 + m0 + g]     += lg;
            lpart[wc * 64 + m0 + 8 + g] += lg8;
        }

        CPA_WAIT0();          // V arrived
        __syncthreads();      // P visible to all warps

        // ---- PV on tensor cores: O[64x512] += P @ V, fp16 k16 steps ----
#pragma unroll
        for (int ks = 0; ks < 4; ++ks) {
            const int k0 = ks * 16;
            uint32_t ap[4][4];
#pragma unroll
            for (int rt = 0; rt < 4; ++rt) {
                uint32_t poff = (uint32_t)((rt * 16 + lrow) * 144 + (k0 + lcol8) * 2);
                ldsm4(ap[rt], sb + OFF_P + poff);
            }
#pragma unroll
            for (int grp = 0; grp < 2; ++grp) {
                uint32_t bv[4];
                uint32_t voff = (uint32_t)((k0 + lrow) * 1040 +
                                           (colbase + grp * 16 + lcol8) * 2);
                ldsm4t(bv, sb + OFF_V + voff);
#pragma unroll
                for (int h = 0; h < 2; ++h) {
                    const int ct = grp * 2 + h;
#pragma unroll
                    for (int rt = 0; rt < 4; ++rt)
                        mma16(acc[rt][ct], ap[rt], bv[h * 2], bv[h * 2 + 1]);
                }
            }
        }
        __syncthreads();      // done reading K/V/P before next tile's cp.async
    }

    // ---- epilogue ----
    if (t < 64) lf[t] = lpart[t] + lpart[64 + t] + lpart[128 + t] + lpart[192 + t];
    __syncthreads();

#pragma unroll
    for (int rt = 0; rt < 4; ++rt) {
        const int r0 = rt * 16 + g;
        const float inv0 = P_UNSC / lf[r0];
        const float inv1 = P_UNSC / lf[r0 + 8];
        float* o0 = out + ((size_t)(b * SDIM + i0 + r0)) * DVDIM;
        float* o1 = out + ((size_t)(b * SDIM + i0 + r0 + 8)) * DVDIM;
#pragma unroll
        for (int ct = 0; ct < 4; ++ct) {
            const int c = colbase + ct * 8 + tid * 2;
            *reinterpret_cast<float2*>(o0 + c) =
                make_float2(acc[rt][ct][0] * inv0, acc[rt][ct][1] * inv0);
            *reinterpret_cast<float2*>(o1 + c) =
                make_float2(acc[rt][ct][2] * inv1, acc[rt][ct][3] * inv1);
        }
    }
}

// ---------------------------------------------------------------------------
extern "C" void kernel_launch(void* const* d_in, const int* in_sizes, int n_in,
                              void* d_out, int out_size) {
    const float* x1 = (const float*)d_in[0];  // [16,2048,64]
    const float* m  = (const float*)d_in[1];  // [64,512]
    const float* n  = (const float*)d_in[2];  // [2048,512]
    const float* q  = (const float*)d_in[3];  // [2048,512]
    float* out = (float*)d_out;               // [16,2048,512]

    cudaFuncSetAttribute(k_attn, cudaFuncAttributeMaxDynamicSharedMemorySize, ATT_SMEM);

    k_build_kt<<<SDIM / 16, 256>>>(m, n);
    k_vr<<<SDIM * DVDIM / 1024, 256>>>(q);
    k_attn<<<BDIM * (SDIM / QB), NT, ATT_SMEM>>>(x1, out);
}